// round 13
// baseline (speedup 1.0000x reference)
#include <cuda_runtime.h>
#include <cuda_fp16.h>
#include <math.h>
#include <stdint.h>

#define NMAX 50000
#define EMAX 800000
#define EPMAX (EMAX + NMAX)

// ---------------- scratch (device globals) ----------------------------------
__device__ __half2 g_xph[(size_t)NMAX * 128]; // x @ W in fp16  [N, 256]
__device__ float g_asrc[NMAX * 4];            // per-node src logits [N,H]
__device__ float g_adst[NMAX * 4];            // per-node dst logits [N,H]
__device__ int   g_cnt[NMAX];                 // in-degree (excl self loop)
__device__ int   g_rowptr[NMAX + 1];          // CSR row pointers
__device__ int   g_cursor[NMAX];              // fill cursors
__device__ int   g_srcidx[EPMAX];             // CSR: src node per slot
__device__ int   g_idx64;                     // 1 if edge_index is int64

__device__ __forceinline__ long long load_idx(const void* ei, long long i, int is64) {
    if (is64) return ((const long long*)ei)[i];
    return (long long)((const int*)ei)[i];
}

__device__ __forceinline__ uint32_t pack2(float a, float b) {
    __half2 h = __floats2half2_rn(a, b);
    return *reinterpret_cast<uint32_t*>(&h);
}

__device__ __forceinline__ float lrelu_exp(float a) {
    a = a > 0.f ? a : 0.2f * a;
    return expf(a);
}

// ---------------- detect index width (1 block) --------------------------------
__global__ void detect_kernel(const unsigned int* __restrict__ ei32, int E) {
    unsigned int v = 0;
    if (threadIdx.x < 128 && threadIdx.x < E) v = ei32[2 * threadIdx.x + 1];
    unsigned int any = __ballot_sync(0xffffffffu, v != 0u);
    __shared__ int flag;
    if (threadIdx.x == 0) flag = 0;
    __syncthreads();
    if ((threadIdx.x & 31) == 0 && any) atomicOr(&flag, 1);
    __syncthreads();
    if (threadIdx.x == 0) g_idx64 = (flag == 0) ? 1 : 0;
}

// ---------------- histogram of destinations (2 edges/thread) ------------------
__global__ void hist_kernel(const void* __restrict__ ei, int E) {
    int i2 = (blockIdx.x * blockDim.x + threadIdx.x) * 2;
    if (i2 >= E) return;
    int is64 = g_idx64;
    int d0, d1 = -1;
    if (is64) {
        const long long* p = (const long long*)ei + E;
        if (i2 + 1 < E) {
            longlong2 v = *reinterpret_cast<const longlong2*>(p + i2);
            d0 = (int)v.x; d1 = (int)v.y;
        } else d0 = (int)p[i2];
    } else {
        const int* p = (const int*)ei + E;
        if (i2 + 1 < E) {
            int2 v = *reinterpret_cast<const int2*>(p + i2);
            d0 = v.x; d1 = v.y;
        } else d0 = p[i2];
    }
    atomicAdd(&g_cnt[d0], 1);
    if (d1 >= 0) atomicAdd(&g_cnt[d1], 1);
}

// ---------------- single-launch scan (1 block, 1024 threads) -------------------
// deg[i] = cnt[i] + 1 (self loop). Writes rowptr/cursor, rowptr[N] at end.
__global__ __launch_bounds__(1024) void scan_kernel(int N) {
    __shared__ int wsum[32];
    __shared__ int carry;
    const int t = threadIdx.x;
    const int lane = t & 31, wpid = t >> 5;
    if (t == 0) carry = 0;
    __syncthreads();

    for (int base = 0; base < N; base += 4096) {
        const int idx = base + t * 4;
        int d0 = 0, d1 = 0, d2 = 0, d3 = 0;
        if (idx + 3 < N) {
            int4 c = *reinterpret_cast<const int4*>(&g_cnt[idx]);
            d0 = c.x + 1; d1 = c.y + 1; d2 = c.z + 1; d3 = c.w + 1;
        } else if (idx < N) {
            d0 = g_cnt[idx] + 1;
            if (idx + 1 < N) d1 = g_cnt[idx + 1] + 1;
            if (idx + 2 < N) d2 = g_cnt[idx + 2] + 1;
            if (idx + 3 < N) d3 = g_cnt[idx + 3] + 1;
        }
        const int sum = d0 + d1 + d2 + d3;
        int inc = sum;
#pragma unroll
        for (int o = 1; o < 32; o <<= 1) {
            int u = __shfl_up_sync(0xffffffffu, inc, o);
            if (lane >= o) inc += u;
        }
        if (lane == 31) wsum[wpid] = inc;
        __syncthreads();
        if (wpid == 0) {
            int w = wsum[lane];
#pragma unroll
            for (int o = 1; o < 32; o <<= 1) {
                int u = __shfl_up_sync(0xffffffffu, w, o);
                if (lane >= o) w += u;
            }
            wsum[lane] = w;
        }
        __syncthreads();
        int excl = carry + (wpid ? wsum[wpid - 1] : 0) + (inc - sum);
        if (idx < N)     { g_rowptr[idx]     = excl; g_cursor[idx]     = excl; } excl += d0;
        if (idx + 1 < N) { g_rowptr[idx + 1] = excl; g_cursor[idx + 1] = excl; } excl += d1;
        if (idx + 2 < N) { g_rowptr[idx + 2] = excl; g_cursor[idx + 2] = excl; } excl += d2;
        if (idx + 3 < N) { g_rowptr[idx + 3] = excl; g_cursor[idx + 3] = excl; }
        __syncthreads();
        if (t == 0) carry += wsum[31];
        __syncthreads();
    }
    if (t == 0) g_rowptr[N] = carry;
}

// ---------------- fp16 mma.sync GEMM + fused attention dots --------------------
// (R10 champion structure: BK=64 two-stage, grid (nb,2))
#define SMEM_BYTES ((4608 + 4352) * 4 + 1024 * 4)

__global__ __launch_bounds__(256, 3) void gemm_mma_kernel(const float* __restrict__ x,
                                                          const float* __restrict__ W,
                                                          const float* __restrict__ att_src,
                                                          const float* __restrict__ att_dst,
                                                          int M) {
    extern __shared__ uint32_t smu[];
    uint32_t* Ah = smu;                    // 4608
    uint32_t* Bh = smu + 4608;             // 4352
    float* fbase = (float*)(smu + 8960);
    float* atts = fbase;
    float* attd = fbase + 256;
    float* part = fbase + 512;

    const int t = threadIdx.x;
    const int m0 = blockIdx.x * 128;
    const int colBase = blockIdx.y * 128;

    if (t < 128) {
        part[t * 4 + 0] = 0.f; part[t * 4 + 1] = 0.f;
        part[t * 4 + 2] = 0.f; part[t * 4 + 3] = 0.f;
    }
    atts[t] = att_src[t];
    attd[t] = att_dst[t];

    const int wid = t >> 5, lane = t & 31;
    const int wr = wid >> 2;
    const int wc = wid & 3;
    const int grp = lane >> 2, t4 = lane & 3;

    float acc[4][4][4];
#pragma unroll
    for (int a = 0; a < 4; a++)
#pragma unroll
        for (int b = 0; b < 4; b++)
#pragma unroll
            for (int c = 0; c < 4; c++) acc[a][b][c] = 0.f;

#pragma unroll
    for (int kt = 0; kt < 128; kt += 64) {
        for (int i = t; i < 128 * 16; i += 256) {
            int row = i >> 4, c4 = (i & 15) * 4;
            float4 v = make_float4(0.f, 0.f, 0.f, 0.f);
            if (m0 + row < M)
                v = *reinterpret_cast<const float4*>(&x[(size_t)(m0 + row) * 128 + kt + c4]);
            uint2 p;
            p.x = pack2(v.x, v.y);
            p.y = pack2(v.z, v.w);
            *reinterpret_cast<uint2*>(&Ah[row * 36 + (c4 >> 1)]) = p;
        }
        for (int i = t; i < 32 * 128; i += 256) {
            int k2 = i >> 7, n = i & 127;
            const float* wp = &W[(size_t)(kt + 2 * k2) * 256 + colBase + n];
            Bh[k2 * 136 + n] = pack2(wp[0], wp[256]);
        }
        __syncthreads();

#pragma unroll
        for (int ks = 0; ks < 4; ks++) {
            const int k2b = ks * 8;
            uint32_t af[4][4];
#pragma unroll
            for (int mf = 0; mf < 4; mf++) {
                const int r = wr * 64 + mf * 16 + grp;
                af[mf][0] = Ah[r * 36 + k2b + t4];
                af[mf][1] = Ah[(r + 8) * 36 + k2b + t4];
                af[mf][2] = Ah[r * 36 + k2b + t4 + 4];
                af[mf][3] = Ah[(r + 8) * 36 + k2b + t4 + 4];
            }
            uint32_t bf[4][2];
#pragma unroll
            for (int nf = 0; nf < 4; nf++) {
                const int c = wc * 32 + nf * 8 + grp;
                bf[nf][0] = Bh[(k2b + t4) * 136 + c];
                bf[nf][1] = Bh[(k2b + t4 + 4) * 136 + c];
            }
#pragma unroll
            for (int mf = 0; mf < 4; mf++)
#pragma unroll
                for (int nf = 0; nf < 4; nf++) {
                    asm volatile(
                        "mma.sync.aligned.m16n8k16.row.col.f32.f16.f16.f32 "
                        "{%0,%1,%2,%3}, {%4,%5,%6,%7}, {%8,%9}, {%0,%1,%2,%3};"
                        : "+f"(acc[mf][nf][0]), "+f"(acc[mf][nf][1]),
                          "+f"(acc[mf][nf][2]), "+f"(acc[mf][nf][3])
                        : "r"(af[mf][0]), "r"(af[mf][1]), "r"(af[mf][2]), "r"(af[mf][3]),
                          "r"(bf[nf][0]), "r"(bf[nf][1]));
                }
        }
        __syncthreads();
    }

    const int head_loc = wc >> 1;
#pragma unroll
    for (int mf = 0; mf < 4; mf++) {
        const int lrow_lo = wr * 64 + mf * 16 + grp;
        const int lrow_hi = lrow_lo + 8;
        const int grow_lo = m0 + lrow_lo;
        const int grow_hi = m0 + lrow_hi;

        float s_lo = 0.f, v_lo = 0.f, s_hi = 0.f, v_hi = 0.f;
#pragma unroll
        for (int nf = 0; nf < 4; nf++) {
            const int col = colBase + wc * 32 + nf * 8 + t4 * 2;
            const float a0 = atts[col], a1 = atts[col + 1];
            const float d0 = attd[col], d1 = attd[col + 1];
            s_lo = fmaf(acc[mf][nf][0], a0, fmaf(acc[mf][nf][1], a1, s_lo));
            v_lo = fmaf(acc[mf][nf][0], d0, fmaf(acc[mf][nf][1], d1, v_lo));
            s_hi = fmaf(acc[mf][nf][2], a0, fmaf(acc[mf][nf][3], a1, s_hi));
            v_hi = fmaf(acc[mf][nf][2], d0, fmaf(acc[mf][nf][3], d1, v_hi));
            if (grow_lo < M)
                g_xph[(size_t)grow_lo * 128 + (col >> 1)] =
                    __floats2half2_rn(acc[mf][nf][0], acc[mf][nf][1]);
            if (grow_hi < M)
                g_xph[(size_t)grow_hi * 128 + (col >> 1)] =
                    __floats2half2_rn(acc[mf][nf][2], acc[mf][nf][3]);
        }
#pragma unroll
        for (int off = 1; off < 4; off <<= 1) {
            s_lo += __shfl_xor_sync(0xffffffffu, s_lo, off);
            v_lo += __shfl_xor_sync(0xffffffffu, v_lo, off);
            s_hi += __shfl_xor_sync(0xffffffffu, s_hi, off);
            v_hi += __shfl_xor_sync(0xffffffffu, v_hi, off);
        }
        if (t4 == 0) {
            atomicAdd(&part[lrow_lo * 4 + head_loc * 2 + 0], s_lo);
            atomicAdd(&part[lrow_lo * 4 + head_loc * 2 + 1], v_lo);
            atomicAdd(&part[lrow_hi * 4 + head_loc * 2 + 0], s_hi);
            atomicAdd(&part[lrow_hi * 4 + head_loc * 2 + 1], v_hi);
        }
    }
    __syncthreads();

    if (t < 128) {
        const int grow = m0 + t;
        if (grow < M) {
            const int hbase = colBase >> 6;
            g_asrc[grow * 4 + hbase + 0] = part[t * 4 + 0];
            g_adst[grow * 4 + hbase + 0] = part[t * 4 + 1];
            g_asrc[grow * 4 + hbase + 1] = part[t * 4 + 2];
            g_adst[grow * 4 + hbase + 1] = part[t * 4 + 3];
        }
    }
}

// ---------------- fill CSR slots: pure index scatter (2 edges/thread) ---------
__global__ __launch_bounds__(256) void fill_kernel(const void* __restrict__ ei, int E, int EP) {
    const int base = (blockIdx.x * blockDim.x + threadIdx.x) * 2;
    if (base >= EP) return;
    const int is64 = g_idx64;
    const bool two = (base + 1 < EP);

    int s0, d0, s1 = 0, d1 = 0;
    if (base + 1 < E) {
        if (is64) {
            const long long* p = (const long long*)ei;
            longlong2 sv = *reinterpret_cast<const longlong2*>(p + base);
            longlong2 dv = *reinterpret_cast<const longlong2*>(p + E + base);
            s0 = (int)sv.x; s1 = (int)sv.y; d0 = (int)dv.x; d1 = (int)dv.y;
        } else {
            const int* p = (const int*)ei;
            int2 sv = *reinterpret_cast<const int2*>(p + base);
            int2 dv = *reinterpret_cast<const int2*>(p + E + base);
            s0 = sv.x; s1 = sv.y; d0 = dv.x; d1 = dv.y;
        }
    } else {
        if (base < E) { s0 = (int)load_idx(ei, base, is64); d0 = (int)load_idx(ei, E + base, is64); }
        else          { s0 = d0 = base - E; }
        if (two) {
            if (base + 1 < E) { s1 = (int)load_idx(ei, base + 1, is64); d1 = (int)load_idx(ei, E + base + 1, is64); }
            else              { s1 = d1 = base + 1 - E; }
        }
    }

    int pos0 = atomicAdd(&g_cursor[d0], 1);
    g_srcidx[pos0] = s0;
    if (two) {
        int pos1 = atomicAdd(&g_cursor[d1], 1);
        g_srcidx[pos1] = s1;
    }
}

// ---------------- aggregate: one warp per destination, exp fused in -----------
__global__ __launch_bounds__(256) void aggregate_kernel(const float* __restrict__ bias,
                                                        float* __restrict__ out, int N) {
    const int warp = (blockIdx.x * blockDim.x + threadIdx.x) >> 5;
    const int lane = threadIdx.x & 31;
    if (warp >= N) return;

    const int start = g_rowptr[warp];
    const int end   = g_rowptr[warp + 1];
    const int h = lane >> 3;

    const float adh = g_adst[warp * 4 + h];  // this node's dst logit for lane's head

    float den = 0.f;
    float acc[8];
#pragma unroll
    for (int j = 0; j < 8; j++) acc[j] = 0.f;

    int pos = start;

    for (; pos + 4 <= end; pos += 4) {
        int s0 = g_srcidx[pos + 0];
        int s1 = g_srcidx[pos + 1];
        int s2 = g_srcidx[pos + 2];
        int s3 = g_srcidx[pos + 3];
        // per-lane 4B gathers of src logits (4 distinct addrs/edge, L2-resident)
        float a0 = g_asrc[s0 * 4 + h];
        float a1 = g_asrc[s1 * 4 + h];
        float a2 = g_asrc[s2 * 4 + h];
        float a3 = g_asrc[s3 * 4 + h];
        uint4 v0 = reinterpret_cast<const uint4*>(g_xph + (size_t)s0 * 128)[lane];
        uint4 v1 = reinterpret_cast<const uint4*>(g_xph + (size_t)s1 * 128)[lane];
        uint4 v2 = reinterpret_cast<const uint4*>(g_xph + (size_t)s2 * 128)[lane];
        uint4 v3 = reinterpret_cast<const uint4*>(g_xph + (size_t)s3 * 128)[lane];
        float c0 = lrelu_exp(a0 + adh);
        float c1 = lrelu_exp(a1 + adh);
        float c2 = lrelu_exp(a2 + adh);
        float c3 = lrelu_exp(a3 + adh);
        den += (c0 + c1) + (c2 + c3);
#pragma unroll
        for (int q = 0; q < 4; q++) {
            uint32_t w0 = (&v0.x)[q], w1 = (&v1.x)[q], w2 = (&v2.x)[q], w3 = (&v3.x)[q];
            float2 f0 = __half22float2(*reinterpret_cast<__half2*>(&w0));
            float2 f1 = __half22float2(*reinterpret_cast<__half2*>(&w1));
            float2 f2 = __half22float2(*reinterpret_cast<__half2*>(&w2));
            float2 f3 = __half22float2(*reinterpret_cast<__half2*>(&w3));
            acc[q * 2 + 0] = fmaf(f0.x, c0, fmaf(f1.x, c1, fmaf(f2.x, c2, fmaf(f3.x, c3, acc[q * 2 + 0]))));
            acc[q * 2 + 1] = fmaf(f0.y, c0, fmaf(f1.y, c1, fmaf(f2.y, c2, fmaf(f3.y, c3, acc[q * 2 + 1]))));
        }
    }
    for (; pos < end; pos++) {
        int s = g_srcidx[pos];
        float a = g_asrc[s * 4 + h];
        uint4 v = reinterpret_cast<const uint4*>(g_xph + (size_t)s * 128)[lane];
        float c = lrelu_exp(a + adh);
        den += c;
#pragma unroll
        for (int q = 0; q < 4; q++) {
            uint32_t w = (&v.x)[q];
            float2 f = __half22float2(*reinterpret_cast<__half2*>(&w));
            acc[q * 2 + 0] = fmaf(f.x, c, acc[q * 2 + 0]);
            acc[q * 2 + 1] = fmaf(f.y, c, acc[q * 2 + 1]);
        }
    }

    const float inv = 1.f / den;
    const float4 b0 = *reinterpret_cast<const float4*>(&bias[lane * 8]);
    const float4 b1 = *reinterpret_cast<const float4*>(&bias[lane * 8 + 4]);
    float* orow = out + (size_t)warp * 256 + lane * 8;
    *reinterpret_cast<float4*>(orow) =
        make_float4(fmaf(acc[0], inv, b0.x), fmaf(acc[1], inv, b0.y),
                    fmaf(acc[2], inv, b0.z), fmaf(acc[3], inv, b0.w));
    *reinterpret_cast<float4*>(orow + 4) =
        make_float4(fmaf(acc[4], inv, b1.x), fmaf(acc[5], inv, b1.y),
                    fmaf(acc[6], inv, b1.z), fmaf(acc[7], inv, b1.w));
}

// ---------------- launch -------------------------------------------------------
extern "C" void kernel_launch(void* const* d_in, const int* in_sizes, int n_in,
                              void* d_out, int out_size) {
    const float* x       = (const float*)d_in[0];
    const float* W       = (const float*)d_in[1];
    const float* att_src = (const float*)d_in[2];
    const float* att_dst = (const float*)d_in[3];
    const float* bias    = (const float*)d_in[4];
    const void*  ei      = d_in[5];
    float*       out     = (float*)d_out;

    const int N  = in_sizes[0] / 128;
    const int E  = in_sizes[5] / 2;
    const int EP = E + N;

    void* cnt_ptr = nullptr;
    cudaGetSymbolAddress(&cnt_ptr, g_cnt);
    cudaMemsetAsync(cnt_ptr, 0, (size_t)N * sizeof(int));

    detect_kernel<<<1, 128>>>((const unsigned int*)ei, E);
    hist_kernel<<<((E + 1) / 2 + 255) / 256, 256>>>(ei, E);
    scan_kernel<<<1, 1024>>>(N);

    cudaFuncSetAttribute(gemm_mma_kernel, cudaFuncAttributeMaxDynamicSharedMemorySize,
                         SMEM_BYTES);
    dim3 ggrid((N + 127) / 128, 2);
    gemm_mma_kernel<<<ggrid, 256, SMEM_BYTES>>>(x, W, att_src, att_dst, N);

    fill_kernel<<<((EP + 1) / 2 + 255) / 256, 256>>>(ei, E, EP);
    aggregate_kernel<<<(N * 32 + 255) / 256, 256>>>(bias, out, N);
}

// round 14
// speedup vs baseline: 1.2337x; 1.2337x over previous
#include <cuda_runtime.h>
#include <cuda_fp16.h>
#include <math.h>
#include <stdint.h>

#define NMAX 50000
#define EMAX 800000
#define EPMAX (EMAX + NMAX)
#define SCAN_B 512
#define NBLK ((NMAX + SCAN_B - 1) / SCAN_B)   // 98

// ---------------- scratch (device globals) ----------------------------------
__device__ __half2 g_xph[(size_t)NMAX * 128]; // x @ W in fp16  [N, 256]
__device__ float g_asrc[NMAX * 4];            // per-node src logits [N,H]
__device__ float g_adst[NMAX * 4];            // per-node dst logits [N,H]
__device__ int   g_cnt[NMAX];                 // in-degree (excl self loop)
__device__ int   g_scan[NMAX];                // block-local inclusive scans
__device__ int   g_bsum[NBLK];                // per-block totals
__device__ int   g_boff[NBLK];                // exclusive block offsets
__device__ int   g_rowptr[NMAX + 1];          // CSR row pointers
__device__ int   g_cursor[NMAX];              // fill cursors
__device__ int   g_srcidx[EPMAX];             // CSR: src node per slot
__device__ float g_ex[(size_t)EPMAX * 4];     // exp(alpha) per slot [.,H]
__device__ int   g_idx64;                     // 1 if edge_index is int64

__device__ __forceinline__ long long load_idx(const void* ei, long long i, int is64) {
    if (is64) return ((const long long*)ei)[i];
    return (long long)((const int*)ei)[i];
}

__device__ __forceinline__ uint32_t pack2(float a, float b) {
    __half2 h = __floats2half2_rn(a, b);
    return *reinterpret_cast<uint32_t*>(&h);
}

__device__ __forceinline__ float pick_h(uint4 e, int h) {
    return (h & 2) ? ((h & 1) ? __uint_as_float(e.w) : __uint_as_float(e.z))
                   : ((h & 1) ? __uint_as_float(e.y) : __uint_as_float(e.x));
}

// ---------------- detect index width (1 block) --------------------------------
__global__ void detect_kernel(const unsigned int* __restrict__ ei32, int E) {
    unsigned int v = 0;
    if (threadIdx.x < 128 && threadIdx.x < E) v = ei32[2 * threadIdx.x + 1];
    unsigned int any = __ballot_sync(0xffffffffu, v != 0u);
    __shared__ int flag;
    if (threadIdx.x == 0) flag = 0;
    __syncthreads();
    if ((threadIdx.x & 31) == 0 && any) atomicOr(&flag, 1);
    __syncthreads();
    if (threadIdx.x == 0) g_idx64 = (flag == 0) ? 1 : 0;
}

// ---------------- histogram of destinations (2 edges/thread) ------------------
__global__ void hist_kernel(const void* __restrict__ ei, int E) {
    int i2 = (blockIdx.x * blockDim.x + threadIdx.x) * 2;
    if (i2 >= E) return;
    int is64 = g_idx64;
    int d0, d1 = -1;
    if (is64) {
        const long long* p = (const long long*)ei + E;
        if (i2 + 1 < E) {
            longlong2 v = *reinterpret_cast<const longlong2*>(p + i2);
            d0 = (int)v.x; d1 = (int)v.y;
        } else d0 = (int)p[i2];
    } else {
        const int* p = (const int*)ei + E;
        if (i2 + 1 < E) {
            int2 v = *reinterpret_cast<const int2*>(p + i2);
            d0 = v.x; d1 = v.y;
        } else d0 = p[i2];
    }
    atomicAdd(&g_cnt[d0], 1);
    if (d1 >= 0) atomicAdd(&g_cnt[d1], 1);
}

// ---------------- 3-phase grid-wide scan (self-loop folded in) -----------------
__global__ __launch_bounds__(SCAN_B) void scan1_kernel(int N) {
    __shared__ int s[SCAN_B];
    const int t = threadIdx.x;
    const int i = blockIdx.x * SCAN_B + t;
    int v = (i < N) ? (g_cnt[i] + 1) : 0;
    s[t] = v;
    __syncthreads();
#pragma unroll
    for (int off = 1; off < SCAN_B; off <<= 1) {
        int u = (t >= off) ? s[t - off] : 0;
        __syncthreads();
        s[t] += u;
        __syncthreads();
    }
    if (i < N) g_scan[i] = s[t];
    if (t == SCAN_B - 1) g_bsum[blockIdx.x] = s[t];
}

__global__ __launch_bounds__(128) void scan2_kernel(int nb) {
    __shared__ int s[128];
    const int t = threadIdx.x;
    s[t] = (t < nb) ? g_bsum[t] : 0;
    __syncthreads();
#pragma unroll
    for (int off = 1; off < 128; off <<= 1) {
        int u = (t >= off) ? s[t - off] : 0;
        __syncthreads();
        s[t] += u;
        __syncthreads();
    }
    if (t < nb) g_boff[t] = (t == 0) ? 0 : s[t - 1];
}

__global__ __launch_bounds__(256) void scan3_kernel(int N) {
    const int i = blockIdx.x * blockDim.x + threadIdx.x;
    if (i >= N) return;
    const int base = g_boff[i / SCAN_B];
    const int incl = base + g_scan[i];
    const int excl = incl - (g_cnt[i] + 1);
    g_rowptr[i] = excl;
    g_cursor[i] = excl;
    if (i == N - 1) g_rowptr[N] = incl;
}

// ---------------- fp16 mma.sync GEMM + fused attention dots --------------------
// (R10 champion structure: BK=64 two-stage, grid (nb,2))
#define SMEM_BYTES ((4608 + 4352) * 4 + 1024 * 4)

__global__ __launch_bounds__(256, 3) void gemm_mma_kernel(const float* __restrict__ x,
                                                          const float* __restrict__ W,
                                                          const float* __restrict__ att_src,
                                                          const float* __restrict__ att_dst,
                                                          int M) {
    extern __shared__ uint32_t smu[];
    uint32_t* Ah = smu;                    // 4608
    uint32_t* Bh = smu + 4608;             // 4352
    float* fbase = (float*)(smu + 8960);
    float* atts = fbase;
    float* attd = fbase + 256;
    float* part = fbase + 512;

    const int t = threadIdx.x;
    const int m0 = blockIdx.x * 128;
    const int colBase = blockIdx.y * 128;

    if (t < 128) {
        part[t * 4 + 0] = 0.f; part[t * 4 + 1] = 0.f;
        part[t * 4 + 2] = 0.f; part[t * 4 + 3] = 0.f;
    }
    atts[t] = att_src[t];
    attd[t] = att_dst[t];

    const int wid = t >> 5, lane = t & 31;
    const int wr = wid >> 2;
    const int wc = wid & 3;
    const int grp = lane >> 2, t4 = lane & 3;

    float acc[4][4][4];
#pragma unroll
    for (int a = 0; a < 4; a++)
#pragma unroll
        for (int b = 0; b < 4; b++)
#pragma unroll
            for (int c = 0; c < 4; c++) acc[a][b][c] = 0.f;

#pragma unroll
    for (int kt = 0; kt < 128; kt += 64) {
        for (int i = t; i < 128 * 16; i += 256) {
            int row = i >> 4, c4 = (i & 15) * 4;
            float4 v = make_float4(0.f, 0.f, 0.f, 0.f);
            if (m0 + row < M)
                v = *reinterpret_cast<const float4*>(&x[(size_t)(m0 + row) * 128 + kt + c4]);
            uint2 p;
            p.x = pack2(v.x, v.y);
            p.y = pack2(v.z, v.w);
            *reinterpret_cast<uint2*>(&Ah[row * 36 + (c4 >> 1)]) = p;
        }
        for (int i = t; i < 32 * 128; i += 256) {
            int k2 = i >> 7, n = i & 127;
            const float* wp = &W[(size_t)(kt + 2 * k2) * 256 + colBase + n];
            Bh[k2 * 136 + n] = pack2(wp[0], wp[256]);
        }
        __syncthreads();

#pragma unroll
        for (int ks = 0; ks < 4; ks++) {
            const int k2b = ks * 8;
            uint32_t af[4][4];
#pragma unroll
            for (int mf = 0; mf < 4; mf++) {
                const int r = wr * 64 + mf * 16 + grp;
                af[mf][0] = Ah[r * 36 + k2b + t4];
                af[mf][1] = Ah[(r + 8) * 36 + k2b + t4];
                af[mf][2] = Ah[r * 36 + k2b + t4 + 4];
                af[mf][3] = Ah[(r + 8) * 36 + k2b + t4 + 4];
            }
            uint32_t bf[4][2];
#pragma unroll
            for (int nf = 0; nf < 4; nf++) {
                const int c = wc * 32 + nf * 8 + grp;
                bf[nf][0] = Bh[(k2b + t4) * 136 + c];
                bf[nf][1] = Bh[(k2b + t4 + 4) * 136 + c];
            }
#pragma unroll
            for (int mf = 0; mf < 4; mf++)
#pragma unroll
                for (int nf = 0; nf < 4; nf++) {
                    asm volatile(
                        "mma.sync.aligned.m16n8k16.row.col.f32.f16.f16.f32 "
                        "{%0,%1,%2,%3}, {%4,%5,%6,%7}, {%8,%9}, {%0,%1,%2,%3};"
                        : "+f"(acc[mf][nf][0]), "+f"(acc[mf][nf][1]),
                          "+f"(acc[mf][nf][2]), "+f"(acc[mf][nf][3])
                        : "r"(af[mf][0]), "r"(af[mf][1]), "r"(af[mf][2]), "r"(af[mf][3]),
                          "r"(bf[nf][0]), "r"(bf[nf][1]));
                }
        }
        __syncthreads();
    }

    const int head_loc = wc >> 1;
#pragma unroll
    for (int mf = 0; mf < 4; mf++) {
        const int lrow_lo = wr * 64 + mf * 16 + grp;
        const int lrow_hi = lrow_lo + 8;
        const int grow_lo = m0 + lrow_lo;
        const int grow_hi = m0 + lrow_hi;

        float s_lo = 0.f, v_lo = 0.f, s_hi = 0.f, v_hi = 0.f;
#pragma unroll
        for (int nf = 0; nf < 4; nf++) {
            const int col = colBase + wc * 32 + nf * 8 + t4 * 2;
            const float a0 = atts[col], a1 = atts[col + 1];
            const float d0 = attd[col], d1 = attd[col + 1];
            s_lo = fmaf(acc[mf][nf][0], a0, fmaf(acc[mf][nf][1], a1, s_lo));
            v_lo = fmaf(acc[mf][nf][0], d0, fmaf(acc[mf][nf][1], d1, v_lo));
            s_hi = fmaf(acc[mf][nf][2], a0, fmaf(acc[mf][nf][3], a1, s_hi));
            v_hi = fmaf(acc[mf][nf][2], d0, fmaf(acc[mf][nf][3], d1, v_hi));
            if (grow_lo < M)
                g_xph[(size_t)grow_lo * 128 + (col >> 1)] =
                    __floats2half2_rn(acc[mf][nf][0], acc[mf][nf][1]);
            if (grow_hi < M)
                g_xph[(size_t)grow_hi * 128 + (col >> 1)] =
                    __floats2half2_rn(acc[mf][nf][2], acc[mf][nf][3]);
        }
#pragma unroll
        for (int off = 1; off < 4; off <<= 1) {
            s_lo += __shfl_xor_sync(0xffffffffu, s_lo, off);
            v_lo += __shfl_xor_sync(0xffffffffu, v_lo, off);
            s_hi += __shfl_xor_sync(0xffffffffu, s_hi, off);
            v_hi += __shfl_xor_sync(0xffffffffu, v_hi, off);
        }
        if (t4 == 0) {
            atomicAdd(&part[lrow_lo * 4 + head_loc * 2 + 0], s_lo);
            atomicAdd(&part[lrow_lo * 4 + head_loc * 2 + 1], v_lo);
            atomicAdd(&part[lrow_hi * 4 + head_loc * 2 + 0], s_hi);
            atomicAdd(&part[lrow_hi * 4 + head_loc * 2 + 1], v_hi);
        }
    }
    __syncthreads();

    if (t < 128) {
        const int grow = m0 + t;
        if (grow < M) {
            const int hbase = colBase >> 6;
            g_asrc[grow * 4 + hbase + 0] = part[t * 4 + 0];
            g_adst[grow * 4 + hbase + 0] = part[t * 4 + 1];
            g_asrc[grow * 4 + hbase + 1] = part[t * 4 + 2];
            g_adst[grow * 4 + hbase + 1] = part[t * 4 + 3];
        }
    }
}

// ---------------- fill CSR slots + edge softmax numerators --------------------
__global__ void fill_kernel(const void* __restrict__ ei, int E, int EP) {
    int i = blockIdx.x * blockDim.x + threadIdx.x;
    if (i >= EP) return;
    int is64 = g_idx64;
    int s, d;
    if (i < E) { s = (int)load_idx(ei, i, is64); d = (int)load_idx(ei, E + i, is64); }
    else       { s = d = i - E; }
    float4 a = reinterpret_cast<const float4*>(g_asrc)[s];
    float4 b = reinterpret_cast<const float4*>(g_adst)[d];
    a.x += b.x; a.y += b.y; a.z += b.z; a.w += b.w;
    a.x = a.x > 0.f ? a.x : 0.2f * a.x;
    a.y = a.y > 0.f ? a.y : 0.2f * a.y;
    a.z = a.z > 0.f ? a.z : 0.2f * a.z;
    a.w = a.w > 0.f ? a.w : 0.2f * a.w;
    float4 ex = make_float4(expf(a.x), expf(a.y), expf(a.z), expf(a.w));
    int pos = atomicAdd(&g_cursor[d], 1);
    g_srcidx[pos] = s;
    reinterpret_cast<float4*>(g_ex)[pos] = ex;
}

// ---------------- aggregate: one warp per destination, single fused pass ------
__global__ __launch_bounds__(256) void aggregate_kernel(const float* __restrict__ bias,
                                                        float* __restrict__ out, int N) {
    const int warp = (blockIdx.x * blockDim.x + threadIdx.x) >> 5;
    const int lane = threadIdx.x & 31;
    if (warp >= N) return;

    const int start = g_rowptr[warp];
    const int end   = g_rowptr[warp + 1];
    const int h = lane >> 3;

    float den = 0.f;
    float acc[8];
#pragma unroll
    for (int j = 0; j < 8; j++) acc[j] = 0.f;

    const uint4* exu = reinterpret_cast<const uint4*>(g_ex);
    int pos = start;

    for (; pos + 4 <= end; pos += 4) {
        int s0 = g_srcidx[pos + 0];
        int s1 = g_srcidx[pos + 1];
        int s2 = g_srcidx[pos + 2];
        int s3 = g_srcidx[pos + 3];
        uint4 e0 = exu[pos + 0];
        uint4 e1 = exu[pos + 1];
        uint4 e2 = exu[pos + 2];
        uint4 e3 = exu[pos + 3];
        uint4 v0 = reinterpret_cast<const uint4*>(g_xph + (size_t)s0 * 128)[lane];
        uint4 v1 = reinterpret_cast<const uint4*>(g_xph + (size_t)s1 * 128)[lane];
        uint4 v2 = reinterpret_cast<const uint4*>(g_xph + (size_t)s2 * 128)[lane];
        uint4 v3 = reinterpret_cast<const uint4*>(g_xph + (size_t)s3 * 128)[lane];
        float c0 = pick_h(e0, h), c1 = pick_h(e1, h), c2 = pick_h(e2, h), c3 = pick_h(e3, h);
        den += (c0 + c1) + (c2 + c3);
#pragma unroll
        for (int q = 0; q < 4; q++) {
            uint32_t w0 = (&v0.x)[q], w1 = (&v1.x)[q], w2 = (&v2.x)[q], w3 = (&v3.x)[q];
            float2 f0 = __half22float2(*reinterpret_cast<__half2*>(&w0));
            float2 f1 = __half22float2(*reinterpret_cast<__half2*>(&w1));
            float2 f2 = __half22float2(*reinterpret_cast<__half2*>(&w2));
            float2 f3 = __half22float2(*reinterpret_cast<__half2*>(&w3));
            acc[q * 2 + 0] = fmaf(f0.x, c0, fmaf(f1.x, c1, fmaf(f2.x, c2, fmaf(f3.x, c3, acc[q * 2 + 0]))));
            acc[q * 2 + 1] = fmaf(f0.y, c0, fmaf(f1.y, c1, fmaf(f2.y, c2, fmaf(f3.y, c3, acc[q * 2 + 1]))));
        }
    }
    for (; pos < end; pos++) {
        int s = g_srcidx[pos];
        uint4 e = exu[pos];
        uint4 v = reinterpret_cast<const uint4*>(g_xph + (size_t)s * 128)[lane];
        float c = pick_h(e, h);
        den += c;
#pragma unroll
        for (int q = 0; q < 4; q++) {
            uint32_t w = (&v.x)[q];
            float2 f = __half22float2(*reinterpret_cast<__half2*>(&w));
            acc[q * 2 + 0] = fmaf(f.x, c, acc[q * 2 + 0]);
            acc[q * 2 + 1] = fmaf(f.y, c, acc[q * 2 + 1]);
        }
    }

    const float inv = 1.f / den;
    const float4 b0 = *reinterpret_cast<const float4*>(&bias[lane * 8]);
    const float4 b1 = *reinterpret_cast<const float4*>(&bias[lane * 8 + 4]);
    float* orow = out + (size_t)warp * 256 + lane * 8;
    *reinterpret_cast<float4*>(orow) =
        make_float4(fmaf(acc[0], inv, b0.x), fmaf(acc[1], inv, b0.y),
                    fmaf(acc[2], inv, b0.z), fmaf(acc[3], inv, b0.w));
    *reinterpret_cast<float4*>(orow + 4) =
        make_float4(fmaf(acc[4], inv, b1.x), fmaf(acc[5], inv, b1.y),
                    fmaf(acc[6], inv, b1.z), fmaf(acc[7], inv, b1.w));
}

// ---------------- launch: fork-join overlap of CSR build vs GEMM ---------------
extern "C" void kernel_launch(void* const* d_in, const int* in_sizes, int n_in,
                              void* d_out, int out_size) {
    const float* x       = (const float*)d_in[0];
    const float* W       = (const float*)d_in[1];
    const float* att_src = (const float*)d_in[2];
    const float* att_dst = (const float*)d_in[3];
    const float* bias    = (const float*)d_in[4];
    const void*  ei      = d_in[5];
    float*       out     = (float*)d_out;

    const int N  = in_sizes[0] / 128;
    const int E  = in_sizes[5] / 2;
    const int EP = E + N;
    const int nb = (N + SCAN_B - 1) / SCAN_B;

    void* cnt_ptr = nullptr;
    cudaGetSymbolAddress(&cnt_ptr, g_cnt);

    // fork: CSR-build branch on a non-blocking side stream
    cudaStream_t s1;
    cudaStreamCreateWithFlags(&s1, cudaStreamNonBlocking);
    cudaEvent_t evFork, evJoin;
    cudaEventCreateWithFlags(&evFork, cudaEventDisableTiming);
    cudaEventCreateWithFlags(&evJoin, cudaEventDisableTiming);

    cudaEventRecord(evFork, 0);
    cudaStreamWaitEvent(s1, evFork, 0);

    cudaMemsetAsync(cnt_ptr, 0, (size_t)N * sizeof(int), s1);
    detect_kernel<<<1, 128, 0, s1>>>((const unsigned int*)ei, E);
    hist_kernel<<<((E + 1) / 2 + 255) / 256, 256, 0, s1>>>(ei, E);
    scan1_kernel<<<nb, SCAN_B, 0, s1>>>(N);
    scan2_kernel<<<1, 128, 0, s1>>>(nb);
    scan3_kernel<<<(N + 255) / 256, 256, 0, s1>>>(N);

    // main branch: GEMM (independent of edges)
    cudaFuncSetAttribute(gemm_mma_kernel, cudaFuncAttributeMaxDynamicSharedMemorySize,
                         SMEM_BYTES);
    dim3 ggrid((N + 127) / 128, 2);
    gemm_mma_kernel<<<ggrid, 256, SMEM_BYTES>>>(x, W, att_src, att_dst, N);

    // join: fill needs scan (s1) + GEMM (stream 0)
    cudaEventRecord(evJoin, s1);
    cudaStreamWaitEvent(0, evJoin, 0);

    fill_kernel<<<(EP + 255) / 256, 256>>>(ei, E, EP);
    aggregate_kernel<<<(N * 32 + 255) / 256, 256>>>(bias, out, N);
}

// round 15
// speedup vs baseline: 1.2701x; 1.0295x over previous
#include <cuda_runtime.h>
#include <cuda_fp16.h>
#include <math.h>
#include <stdint.h>

#define NMAX 50000
#define EMAX 800000
#define EPMAX (EMAX + NMAX)
#define SCAN_B 512
#define NBLK ((NMAX + SCAN_B - 1) / SCAN_B)   // 98

// ---------------- scratch (device globals) ----------------------------------
__device__ __half2 g_xph[(size_t)NMAX * 128]; // x @ W in fp16  [N, 256]
__device__ float g_asrc[NMAX * 4];            // per-node src logits [N,H]
__device__ float g_adst[NMAX * 4];            // per-node dst logits [N,H]
__device__ int   g_cnt[NMAX];                 // in-degree (excl self loop)
__device__ int   g_scan[NMAX];                // block-local inclusive scans
__device__ int   g_bsum[NBLK];                // per-block totals
__device__ int   g_boff[NBLK];                // exclusive block offsets
__device__ int   g_rowptr[NMAX + 1];          // CSR row pointers
__device__ int   g_cursor[NMAX];              // fill cursors
__device__ int2  g_sd[EPMAX];                 // CSR: (src,dst) per slot
__device__ float g_ex[(size_t)EPMAX * 4];     // exp(alpha) per slot [.,H]
__device__ int   g_idx64;                     // 1 if edge_index is int64

__device__ __forceinline__ long long load_idx(const void* ei, long long i, int is64) {
    if (is64) return ((const long long*)ei)[i];
    return (long long)((const int*)ei)[i];
}

__device__ __forceinline__ uint32_t pack2(float a, float b) {
    __half2 h = __floats2half2_rn(a, b);
    return *reinterpret_cast<uint32_t*>(&h);
}

__device__ __forceinline__ float pick_h(uint4 e, int h) {
    return (h & 2) ? ((h & 1) ? __uint_as_float(e.w) : __uint_as_float(e.z))
                   : ((h & 1) ? __uint_as_float(e.y) : __uint_as_float(e.x));
}

// ---------------- detect index width (1 block) --------------------------------
__global__ void detect_kernel(const unsigned int* __restrict__ ei32, int E) {
    unsigned int v = 0;
    if (threadIdx.x < 128 && threadIdx.x < E) v = ei32[2 * threadIdx.x + 1];
    unsigned int any = __ballot_sync(0xffffffffu, v != 0u);
    __shared__ int flag;
    if (threadIdx.x == 0) flag = 0;
    __syncthreads();
    if ((threadIdx.x & 31) == 0 && any) atomicOr(&flag, 1);
    __syncthreads();
    if (threadIdx.x == 0) g_idx64 = (flag == 0) ? 1 : 0;
}

// ---------------- histogram of destinations (2 edges/thread) ------------------
__global__ void hist_kernel(const void* __restrict__ ei, int E) {
    int i2 = (blockIdx.x * blockDim.x + threadIdx.x) * 2;
    if (i2 >= E) return;
    int is64 = g_idx64;
    int d0, d1 = -1;
    if (is64) {
        const long long* p = (const long long*)ei + E;
        if (i2 + 1 < E) {
            longlong2 v = *reinterpret_cast<const longlong2*>(p + i2);
            d0 = (int)v.x; d1 = (int)v.y;
        } else d0 = (int)p[i2];
    } else {
        const int* p = (const int*)ei + E;
        if (i2 + 1 < E) {
            int2 v = *reinterpret_cast<const int2*>(p + i2);
            d0 = v.x; d1 = v.y;
        } else d0 = p[i2];
    }
    atomicAdd(&g_cnt[d0], 1);
    if (d1 >= 0) atomicAdd(&g_cnt[d1], 1);
}

// ---------------- 3-phase grid-wide scan (self-loop folded in) -----------------
__global__ __launch_bounds__(SCAN_B) void scan1_kernel(int N) {
    __shared__ int s[SCAN_B];
    const int t = threadIdx.x;
    const int i = blockIdx.x * SCAN_B + t;
    int v = (i < N) ? (g_cnt[i] + 1) : 0;
    s[t] = v;
    __syncthreads();
#pragma unroll
    for (int off = 1; off < SCAN_B; off <<= 1) {
        int u = (t >= off) ? s[t - off] : 0;
        __syncthreads();
        s[t] += u;
        __syncthreads();
    }
    if (i < N) g_scan[i] = s[t];
    if (t == SCAN_B - 1) g_bsum[blockIdx.x] = s[t];
}

__global__ __launch_bounds__(128) void scan2_kernel(int nb) {
    __shared__ int s[128];
    const int t = threadIdx.x;
    s[t] = (t < nb) ? g_bsum[t] : 0;
    __syncthreads();
#pragma unroll
    for (int off = 1; off < 128; off <<= 1) {
        int u = (t >= off) ? s[t - off] : 0;
        __syncthreads();
        s[t] += u;
        __syncthreads();
    }
    if (t < nb) g_boff[t] = (t == 0) ? 0 : s[t - 1];
}

__global__ __launch_bounds__(256) void scan3_kernel(int N) {
    const int i = blockIdx.x * blockDim.x + threadIdx.x;
    if (i >= N) return;
    const int base = g_boff[i / SCAN_B];
    const int incl = base + g_scan[i];
    const int excl = incl - (g_cnt[i] + 1);
    g_rowptr[i] = excl;
    g_cursor[i] = excl;
    if (i == N - 1) g_rowptr[N] = incl;
}

// ---------------- fill CSR slots: index-only scatter (no GEMM dependency) -----
__global__ void fill_idx_kernel(const void* __restrict__ ei, int E, int EP) {
    int i = blockIdx.x * blockDim.x + threadIdx.x;
    if (i >= EP) return;
    int is64 = g_idx64;
    int s, d;
    if (i < E) { s = (int)load_idx(ei, i, is64); d = (int)load_idx(ei, E + i, is64); }
    else       { s = d = i - E; }
    int pos = atomicAdd(&g_cursor[d], 1);
    g_sd[pos] = make_int2(s, d);
}

// ---------------- ex: pos-parallel softmax numerators (after GEMM) ------------
__global__ __launch_bounds__(256) void ex_kernel(int EP) {
    int pos = blockIdx.x * blockDim.x + threadIdx.x;
    if (pos >= EP) return;
    int2 sd = g_sd[pos];                                   // coalesced
    float4 a = reinterpret_cast<const float4*>(g_asrc)[sd.x];
    float4 b = reinterpret_cast<const float4*>(g_adst)[sd.y];
    a.x += b.x; a.y += b.y; a.z += b.z; a.w += b.w;
    a.x = a.x > 0.f ? a.x : 0.2f * a.x;
    a.y = a.y > 0.f ? a.y : 0.2f * a.y;
    a.z = a.z > 0.f ? a.z : 0.2f * a.z;
    a.w = a.w > 0.f ? a.w : 0.2f * a.w;
    reinterpret_cast<float4*>(g_ex)[pos] =
        make_float4(expf(a.x), expf(a.y), expf(a.z), expf(a.w));  // coalesced
}

// ---------------- fp16 mma.sync GEMM + fused attention dots --------------------
#define SMEM_BYTES ((4608 + 4352) * 4 + 1024 * 4)

__global__ __launch_bounds__(256, 3) void gemm_mma_kernel(const float* __restrict__ x,
                                                          const float* __restrict__ W,
                                                          const float* __restrict__ att_src,
                                                          const float* __restrict__ att_dst,
                                                          int M) {
    extern __shared__ uint32_t smu[];
    uint32_t* Ah = smu;                    // 4608
    uint32_t* Bh = smu + 4608;             // 4352
    float* fbase = (float*)(smu + 8960);
    float* atts = fbase;
    float* attd = fbase + 256;
    float* part = fbase + 512;

    const int t = threadIdx.x;
    const int m0 = blockIdx.x * 128;
    const int colBase = blockIdx.y * 128;

    if (t < 128) {
        part[t * 4 + 0] = 0.f; part[t * 4 + 1] = 0.f;
        part[t * 4 + 2] = 0.f; part[t * 4 + 3] = 0.f;
    }
    atts[t] = att_src[t];
    attd[t] = att_dst[t];

    const int wid = t >> 5, lane = t & 31;
    const int wr = wid >> 2;
    const int wc = wid & 3;
    const int grp = lane >> 2, t4 = lane & 3;

    float acc[4][4][4];
#pragma unroll
    for (int a = 0; a < 4; a++)
#pragma unroll
        for (int b = 0; b < 4; b++)
#pragma unroll
            for (int c = 0; c < 4; c++) acc[a][b][c] = 0.f;

#pragma unroll
    for (int kt = 0; kt < 128; kt += 64) {
        for (int i = t; i < 128 * 16; i += 256) {
            int row = i >> 4, c4 = (i & 15) * 4;
            float4 v = make_float4(0.f, 0.f, 0.f, 0.f);
            if (m0 + row < M)
                v = *reinterpret_cast<const float4*>(&x[(size_t)(m0 + row) * 128 + kt + c4]);
            uint2 p;
            p.x = pack2(v.x, v.y);
            p.y = pack2(v.z, v.w);
            *reinterpret_cast<uint2*>(&Ah[row * 36 + (c4 >> 1)]) = p;
        }
        for (int i = t; i < 32 * 128; i += 256) {
            int k2 = i >> 7, n = i & 127;
            const float* wp = &W[(size_t)(kt + 2 * k2) * 256 + colBase + n];
            Bh[k2 * 136 + n] = pack2(wp[0], wp[256]);
        }
        __syncthreads();

#pragma unroll
        for (int ks = 0; ks < 4; ks++) {
            const int k2b = ks * 8;
            uint32_t af[4][4];
#pragma unroll
            for (int mf = 0; mf < 4; mf++) {
                const int r = wr * 64 + mf * 16 + grp;
                af[mf][0] = Ah[r * 36 + k2b + t4];
                af[mf][1] = Ah[(r + 8) * 36 + k2b + t4];
                af[mf][2] = Ah[r * 36 + k2b + t4 + 4];
                af[mf][3] = Ah[(r + 8) * 36 + k2b + t4 + 4];
            }
            uint32_t bf[4][2];
#pragma unroll
            for (int nf = 0; nf < 4; nf++) {
                const int c = wc * 32 + nf * 8 + grp;
                bf[nf][0] = Bh[(k2b + t4) * 136 + c];
                bf[nf][1] = Bh[(k2b + t4 + 4) * 136 + c];
            }
#pragma unroll
            for (int mf = 0; mf < 4; mf++)
#pragma unroll
                for (int nf = 0; nf < 4; nf++) {
                    asm volatile(
                        "mma.sync.aligned.m16n8k16.row.col.f32.f16.f16.f32 "
                        "{%0,%1,%2,%3}, {%4,%5,%6,%7}, {%8,%9}, {%0,%1,%2,%3};"
                        : "+f"(acc[mf][nf][0]), "+f"(acc[mf][nf][1]),
                          "+f"(acc[mf][nf][2]), "+f"(acc[mf][nf][3])
                        : "r"(af[mf][0]), "r"(af[mf][1]), "r"(af[mf][2]), "r"(af[mf][3]),
                          "r"(bf[nf][0]), "r"(bf[nf][1]));
                }
        }
        __syncthreads();
    }

    const int head_loc = wc >> 1;
#pragma unroll
    for (int mf = 0; mf < 4; mf++) {
        const int lrow_lo = wr * 64 + mf * 16 + grp;
        const int lrow_hi = lrow_lo + 8;
        const int grow_lo = m0 + lrow_lo;
        const int grow_hi = m0 + lrow_hi;

        float s_lo = 0.f, v_lo = 0.f, s_hi = 0.f, v_hi = 0.f;
#pragma unroll
        for (int nf = 0; nf < 4; nf++) {
            const int col = colBase + wc * 32 + nf * 8 + t4 * 2;
            const float a0 = atts[col], a1 = atts[col + 1];
            const float d0 = attd[col], d1 = attd[col + 1];
            s_lo = fmaf(acc[mf][nf][0], a0, fmaf(acc[mf][nf][1], a1, s_lo));
            v_lo = fmaf(acc[mf][nf][0], d0, fmaf(acc[mf][nf][1], d1, v_lo));
            s_hi = fmaf(acc[mf][nf][2], a0, fmaf(acc[mf][nf][3], a1, s_hi));
            v_hi = fmaf(acc[mf][nf][2], d0, fmaf(acc[mf][nf][3], d1, v_hi));
            if (grow_lo < M)
                g_xph[(size_t)grow_lo * 128 + (col >> 1)] =
                    __floats2half2_rn(acc[mf][nf][0], acc[mf][nf][1]);
            if (grow_hi < M)
                g_xph[(size_t)grow_hi * 128 + (col >> 1)] =
                    __floats2half2_rn(acc[mf][nf][2], acc[mf][nf][3]);
        }
#pragma unroll
        for (int off = 1; off < 4; off <<= 1) {
            s_lo += __shfl_xor_sync(0xffffffffu, s_lo, off);
            v_lo += __shfl_xor_sync(0xffffffffu, v_lo, off);
            s_hi += __shfl_xor_sync(0xffffffffu, s_hi, off);
            v_hi += __shfl_xor_sync(0xffffffffu, v_hi, off);
        }
        if (t4 == 0) {
            atomicAdd(&part[lrow_lo * 4 + head_loc * 2 + 0], s_lo);
            atomicAdd(&part[lrow_lo * 4 + head_loc * 2 + 1], v_lo);
            atomicAdd(&part[lrow_hi * 4 + head_loc * 2 + 0], s_hi);
            atomicAdd(&part[lrow_hi * 4 + head_loc * 2 + 1], v_hi);
        }
    }
    __syncthreads();

    if (t < 128) {
        const int grow = m0 + t;
        if (grow < M) {
            const int hbase = colBase >> 6;
            g_asrc[grow * 4 + hbase + 0] = part[t * 4 + 0];
            g_adst[grow * 4 + hbase + 0] = part[t * 4 + 1];
            g_asrc[grow * 4 + hbase + 1] = part[t * 4 + 2];
            g_adst[grow * 4 + hbase + 1] = part[t * 4 + 3];
        }
    }
}

// ---------------- aggregate: one warp per destination, single fused pass ------
__global__ __launch_bounds__(256) void aggregate_kernel(const float* __restrict__ bias,
                                                        float* __restrict__ out, int N) {
    const int warp = (blockIdx.x * blockDim.x + threadIdx.x) >> 5;
    const int lane = threadIdx.x & 31;
    if (warp >= N) return;

    const int start = g_rowptr[warp];
    const int end   = g_rowptr[warp + 1];
    const int h = lane >> 3;

    float den = 0.f;
    float acc[8];
#pragma unroll
    for (int j = 0; j < 8; j++) acc[j] = 0.f;

    const uint4* exu = reinterpret_cast<const uint4*>(g_ex);
    int pos = start;

    for (; pos + 4 <= end; pos += 4) {
        int s0 = g_sd[pos + 0].x;
        int s1 = g_sd[pos + 1].x;
        int s2 = g_sd[pos + 2].x;
        int s3 = g_sd[pos + 3].x;
        uint4 e0 = exu[pos + 0];
        uint4 e1 = exu[pos + 1];
        uint4 e2 = exu[pos + 2];
        uint4 e3 = exu[pos + 3];
        uint4 v0 = reinterpret_cast<const uint4*>(g_xph + (size_t)s0 * 128)[lane];
        uint4 v1 = reinterpret_cast<const uint4*>(g_xph + (size_t)s1 * 128)[lane];
        uint4 v2 = reinterpret_cast<const uint4*>(g_xph + (size_t)s2 * 128)[lane];
        uint4 v3 = reinterpret_cast<const uint4*>(g_xph + (size_t)s3 * 128)[lane];
        float c0 = pick_h(e0, h), c1 = pick_h(e1, h), c2 = pick_h(e2, h), c3 = pick_h(e3, h);
        den += (c0 + c1) + (c2 + c3);
#pragma unroll
        for (int q = 0; q < 4; q++) {
            uint32_t w0 = (&v0.x)[q], w1 = (&v1.x)[q], w2 = (&v2.x)[q], w3 = (&v3.x)[q];
            float2 f0 = __half22float2(*reinterpret_cast<__half2*>(&w0));
            float2 f1 = __half22float2(*reinterpret_cast<__half2*>(&w1));
            float2 f2 = __half22float2(*reinterpret_cast<__half2*>(&w2));
            float2 f3 = __half22float2(*reinterpret_cast<__half2*>(&w3));
            acc[q * 2 + 0] = fmaf(f0.x, c0, fmaf(f1.x, c1, fmaf(f2.x, c2, fmaf(f3.x, c3, acc[q * 2 + 0]))));
            acc[q * 2 + 1] = fmaf(f0.y, c0, fmaf(f1.y, c1, fmaf(f2.y, c2, fmaf(f3.y, c3, acc[q * 2 + 1]))));
        }
    }
    for (; pos < end; pos++) {
        int s = g_sd[pos].x;
        uint4 e = exu[pos];
        uint4 v = reinterpret_cast<const uint4*>(g_xph + (size_t)s * 128)[lane];
        float c = pick_h(e, h);
        den += c;
#pragma unroll
        for (int q = 0; q < 4; q++) {
            uint32_t w = (&v.x)[q];
            float2 f = __half22float2(*reinterpret_cast<__half2*>(&w));
            acc[q * 2 + 0] = fmaf(f.x, c, acc[q * 2 + 0]);
            acc[q * 2 + 1] = fmaf(f.y, c, acc[q * 2 + 1]);
        }
    }

    const float inv = 1.f / den;
    const float4 b0 = *reinterpret_cast<const float4*>(&bias[lane * 8]);
    const float4 b1 = *reinterpret_cast<const float4*>(&bias[lane * 8 + 4]);
    float* orow = out + (size_t)warp * 256 + lane * 8;
    *reinterpret_cast<float4*>(orow) =
        make_float4(fmaf(acc[0], inv, b0.x), fmaf(acc[1], inv, b0.y),
                    fmaf(acc[2], inv, b0.z), fmaf(acc[3], inv, b0.w));
    *reinterpret_cast<float4*>(orow + 4) =
        make_float4(fmaf(acc[4], inv, b1.x), fmaf(acc[5], inv, b1.y),
                    fmaf(acc[6], inv, b1.z), fmaf(acc[7], inv, b1.w));
}

// ---------------- launch: fork-join, CSR+fill_idx overlapped with GEMM ---------
extern "C" void kernel_launch(void* const* d_in, const int* in_sizes, int n_in,
                              void* d_out, int out_size) {
    const float* x       = (const float*)d_in[0];
    const float* W       = (const float*)d_in[1];
    const float* att_src = (const float*)d_in[2];
    const float* att_dst = (const float*)d_in[3];
    const float* bias    = (const float*)d_in[4];
    const void*  ei      = d_in[5];
    float*       out     = (float*)d_out;

    const int N  = in_sizes[0] / 128;
    const int E  = in_sizes[5] / 2;
    const int EP = E + N;
    const int nb = (N + SCAN_B - 1) / SCAN_B;

    void* cnt_ptr = nullptr;
    cudaGetSymbolAddress(&cnt_ptr, g_cnt);

    cudaStream_t s1;
    cudaStreamCreateWithFlags(&s1, cudaStreamNonBlocking);
    cudaEvent_t evFork, evJoin;
    cudaEventCreateWithFlags(&evFork, cudaEventDisableTiming);
    cudaEventCreateWithFlags(&evJoin, cudaEventDisableTiming);

    cudaEventRecord(evFork, 0);
    cudaStreamWaitEvent(s1, evFork, 0);

    // CSR branch (independent of GEMM): memset, detect, hist, scan, fill_idx
    cudaMemsetAsync(cnt_ptr, 0, (size_t)N * sizeof(int), s1);
    detect_kernel<<<1, 128, 0, s1>>>((const unsigned int*)ei, E);
    hist_kernel<<<((E + 1) / 2 + 255) / 256, 256, 0, s1>>>(ei, E);
    scan1_kernel<<<nb, SCAN_B, 0, s1>>>(N);
    scan2_kernel<<<1, 128, 0, s1>>>(nb);
    scan3_kernel<<<(N + 255) / 256, 256, 0, s1>>>(N);
    fill_idx_kernel<<<(EP + 255) / 256, 256, 0, s1>>>(ei, E, EP);

    // main branch: GEMM
    cudaFuncSetAttribute(gemm_mma_kernel, cudaFuncAttributeMaxDynamicSharedMemorySize,
                         SMEM_BYTES);
    dim3 ggrid((N + 127) / 128, 2);
    gemm_mma_kernel<<<ggrid, 256, SMEM_BYTES>>>(x, W, att_src, att_dst, N);

    // join: ex needs fill_idx (s1) + GEMM logits (stream 0)
    cudaEventRecord(evJoin, s1);
    cudaStreamWaitEvent(0, evJoin, 0);

    ex_kernel<<<(EP + 255) / 256, 256>>>(EP);
    aggregate_kernel<<<(N * 32 + 255) / 256, 256>>>(bias, out, N);
}

// round 16
// speedup vs baseline: 1.3058x; 1.0281x over previous
#include <cuda_runtime.h>
#include <cuda_fp16.h>
#include <math.h>
#include <stdint.h>

#define NMAX 50000
#define EMAX 800000
#define EPMAX (EMAX + NMAX)
#define SCAN_B 512
#define NBLK ((NMAX + SCAN_B - 1) / SCAN_B)   // 98

// ---------------- scratch (device globals) ----------------------------------
__device__ __half2 g_xph[(size_t)NMAX * 128]; // x @ W in fp16  [N, 256]
__device__ float g_asrc[NMAX * 4];            // per-node src logits [N,H]
__device__ float g_adst[NMAX * 4];            // per-node dst logits [N,H]
__device__ int   g_cnt[NMAX];                 // in-degree (excl self loop)
__device__ int   g_scan[NMAX];                // block-local inclusive scans
__device__ int   g_bsum[NBLK];                // per-block totals
__device__ int   g_boff[NBLK];                // exclusive block offsets
__device__ int   g_rowptr[NMAX + 1];          // CSR row pointers
__device__ int   g_cursor[NMAX];              // fill cursors
__device__ int2  g_sd[EPMAX];                 // CSR: (src,dst) per slot
__device__ float g_ex[(size_t)EPMAX * 4];     // exp(alpha) per slot [.,H]
__device__ int   g_idx64;                     // 1 if edge_index is int64

__device__ __forceinline__ long long load_idx(const void* ei, long long i, int is64) {
    if (is64) return ((const long long*)ei)[i];
    return (long long)((const int*)ei)[i];
}

__device__ __forceinline__ uint32_t pack2(float a, float b) {
    __half2 h = __floats2half2_rn(a, b);
    return *reinterpret_cast<uint32_t*>(&h);
}

__device__ __forceinline__ float pick_h(uint4 e, int h) {
    return (h & 2) ? ((h & 1) ? __uint_as_float(e.w) : __uint_as_float(e.z))
                   : ((h & 1) ? __uint_as_float(e.y) : __uint_as_float(e.x));
}

__device__ __forceinline__ void ldm_x4(uint32_t* r, uint32_t saddr) {
    asm volatile("ldmatrix.sync.aligned.m8n8.x4.shared.b16 {%0,%1,%2,%3}, [%4];"
                 : "=r"(r[0]), "=r"(r[1]), "=r"(r[2]), "=r"(r[3]) : "r"(saddr));
}

// ---------------- detect index width (1 block) --------------------------------
__global__ void detect_kernel(const unsigned int* __restrict__ ei32, int E) {
    unsigned int v = 0;
    if (threadIdx.x < 128 && threadIdx.x < E) v = ei32[2 * threadIdx.x + 1];
    unsigned int any = __ballot_sync(0xffffffffu, v != 0u);
    __shared__ int flag;
    if (threadIdx.x == 0) flag = 0;
    __syncthreads();
    if ((threadIdx.x & 31) == 0 && any) atomicOr(&flag, 1);
    __syncthreads();
    if (threadIdx.x == 0) g_idx64 = (flag == 0) ? 1 : 0;
}

// ---------------- histogram of destinations (2 edges/thread) ------------------
__global__ void hist_kernel(const void* __restrict__ ei, int E) {
    int i2 = (blockIdx.x * blockDim.x + threadIdx.x) * 2;
    if (i2 >= E) return;
    int is64 = g_idx64;
    int d0, d1 = -1;
    if (is64) {
        const long long* p = (const long long*)ei + E;
        if (i2 + 1 < E) {
            longlong2 v = *reinterpret_cast<const longlong2*>(p + i2);
            d0 = (int)v.x; d1 = (int)v.y;
        } else d0 = (int)p[i2];
    } else {
        const int* p = (const int*)ei + E;
        if (i2 + 1 < E) {
            int2 v = *reinterpret_cast<const int2*>(p + i2);
            d0 = v.x; d1 = v.y;
        } else d0 = p[i2];
    }
    atomicAdd(&g_cnt[d0], 1);
    if (d1 >= 0) atomicAdd(&g_cnt[d1], 1);
}

// ---------------- 3-phase grid-wide scan (self-loop folded in) -----------------
__global__ __launch_bounds__(SCAN_B) void scan1_kernel(int N) {
    __shared__ int s[SCAN_B];
    const int t = threadIdx.x;
    const int i = blockIdx.x * SCAN_B + t;
    int v = (i < N) ? (g_cnt[i] + 1) : 0;
    s[t] = v;
    __syncthreads();
#pragma unroll
    for (int off = 1; off < SCAN_B; off <<= 1) {
        int u = (t >= off) ? s[t - off] : 0;
        __syncthreads();
        s[t] += u;
        __syncthreads();
    }
    if (i < N) g_scan[i] = s[t];
    if (t == SCAN_B - 1) g_bsum[blockIdx.x] = s[t];
}

__global__ __launch_bounds__(128) void scan2_kernel(int nb) {
    __shared__ int s[128];
    const int t = threadIdx.x;
    s[t] = (t < nb) ? g_bsum[t] : 0;
    __syncthreads();
#pragma unroll
    for (int off = 1; off < 128; off <<= 1) {
        int u = (t >= off) ? s[t - off] : 0;
        __syncthreads();
        s[t] += u;
        __syncthreads();
    }
    if (t < nb) g_boff[t] = (t == 0) ? 0 : s[t - 1];
}

__global__ __launch_bounds__(256) void scan3_kernel(int N) {
    const int i = blockIdx.x * blockDim.x + threadIdx.x;
    if (i >= N) return;
    const int base = g_boff[i / SCAN_B];
    const int incl = base + g_scan[i];
    const int excl = incl - (g_cnt[i] + 1);
    g_rowptr[i] = excl;
    g_cursor[i] = excl;
    if (i == N - 1) g_rowptr[N] = incl;
}

// ---------------- fill CSR slots: index-only scatter (no GEMM dependency) -----
__global__ void fill_idx_kernel(const void* __restrict__ ei, int E, int EP) {
    int i = blockIdx.x * blockDim.x + threadIdx.x;
    if (i >= EP) return;
    int is64 = g_idx64;
    int s, d;
    if (i < E) { s = (int)load_idx(ei, i, is64); d = (int)load_idx(ei, E + i, is64); }
    else       { s = d = i - E; }
    int pos = atomicAdd(&g_cursor[d], 1);
    g_sd[pos] = make_int2(s, d);
}

// ---------------- ex: pos-parallel softmax numerators (after GEMM) ------------
__global__ __launch_bounds__(256) void ex_kernel(int EP) {
    int pos = blockIdx.x * blockDim.x + threadIdx.x;
    if (pos >= EP) return;
    int2 sd = g_sd[pos];
    float4 a = reinterpret_cast<const float4*>(g_asrc)[sd.x];
    float4 b = reinterpret_cast<const float4*>(g_adst)[sd.y];
    a.x += b.x; a.y += b.y; a.z += b.z; a.w += b.w;
    a.x = a.x > 0.f ? a.x : 0.2f * a.x;
    a.y = a.y > 0.f ? a.y : 0.2f * a.y;
    a.z = a.z > 0.f ? a.z : 0.2f * a.z;
    a.w = a.w > 0.f ? a.w : 0.2f * a.w;
    reinterpret_cast<float4*>(g_ex)[pos] =
        make_float4(expf(a.x), expf(a.y), expf(a.z), expf(a.w));
}

// ---------------- fp16 mma.sync GEMM + fused attention dots --------------------
// Ah: 128 rows x 32 k2, pitch 36 u32 (4608). Bh2: 128 n-cols x 32 k2, pitch 36
// (4608) -- n-major so both operands feed ldmatrix.m8n8.x4.
#define SMEM_BYTES ((4608 + 4608) * 4 + 1024 * 4)

__global__ __launch_bounds__(256, 3) void gemm_mma_kernel(const float* __restrict__ x,
                                                          const float* __restrict__ W,
                                                          const float* __restrict__ att_src,
                                                          const float* __restrict__ att_dst,
                                                          int M) {
    extern __shared__ uint32_t smu[];
    uint32_t* Ah  = smu;                   // 4608
    uint32_t* Bh2 = smu + 4608;            // 4608
    float* fbase = (float*)(smu + 9216);
    float* atts = fbase;
    float* attd = fbase + 256;
    float* part = fbase + 512;

    const int t = threadIdx.x;
    const int m0 = blockIdx.x * 128;
    const int colBase = blockIdx.y * 128;

    if (t < 128) {
        part[t * 4 + 0] = 0.f; part[t * 4 + 1] = 0.f;
        part[t * 4 + 2] = 0.f; part[t * 4 + 3] = 0.f;
    }
    atts[t] = att_src[t];
    attd[t] = att_dst[t];

    const int wid = t >> 5, lane = t & 31;
    const int wr = wid >> 2;
    const int wc = wid & 3;
    const int grp = lane >> 2, t4 = lane & 3;

    // ldmatrix per-lane address components: matrix id lm (0..3), row-in-matrix lj
    const int lm = lane >> 3, lj = lane & 7;
    const uint32_t ah_s  = (uint32_t)__cvta_generic_to_shared(Ah);
    const uint32_t bh_s  = (uint32_t)__cvta_generic_to_shared(Bh2);
    // A: row = wr*64 + mf*16 + (lm&1)*8 + lj ; kw = k2b + (lm>>1)*4
    const uint32_t aBase = ah_s + (uint32_t)(((wr * 64 + (lm & 1) * 8 + lj) * 36 + (lm >> 1) * 4) * 4);
    // B: col = wc*32 + p*16 + (lm>>1)*8 + lj ; kw = k2b + (lm&1)*4
    const uint32_t bBase = bh_s + (uint32_t)(((wc * 32 + (lm >> 1) * 8 + lj) * 36 + (lm & 1) * 4) * 4);

    float acc[4][4][4];
#pragma unroll
    for (int a = 0; a < 4; a++)
#pragma unroll
        for (int b = 0; b < 4; b++)
#pragma unroll
            for (int c = 0; c < 4; c++) acc[a][b][c] = 0.f;

#pragma unroll
    for (int kt = 0; kt < 128; kt += 64) {
        // A stage: 128 rows x 64 k (16 float4 per row)
        for (int i = t; i < 128 * 16; i += 256) {
            int row = i >> 4, c4 = (i & 15) * 4;
            float4 v = make_float4(0.f, 0.f, 0.f, 0.f);
            if (m0 + row < M)
                v = *reinterpret_cast<const float4*>(&x[(size_t)(m0 + row) * 128 + kt + c4]);
            uint2 p;
            p.x = pack2(v.x, v.y);
            p.y = pack2(v.z, v.w);
            *reinterpret_cast<uint2*>(&Ah[row * 36 + (c4 >> 1)]) = p;
        }
        // B stage (n-major): Bh2[n*36 + k2] = half2(W[kt+2k2][n], W[kt+2k2+1][n])
        for (int i = t; i < 32 * 128; i += 256) {
            int k2 = i >> 7, n = i & 127;
            const float* wp = &W[(size_t)(kt + 2 * k2) * 256 + colBase + n];
            Bh2[n * 36 + k2] = pack2(wp[0], wp[256]);
        }
        __syncthreads();

#pragma unroll
        for (int ks = 0; ks < 4; ks++) {
            const uint32_t kOff = (uint32_t)(ks * 8 * 4);   // k2b*4 bytes
            uint32_t af[4][4];
#pragma unroll
            for (int mf = 0; mf < 4; mf++)
                ldm_x4(af[mf], aBase + (uint32_t)(mf * 576 * 4) + kOff);
            uint32_t bf[4][2];
#pragma unroll
            for (int p = 0; p < 2; p++) {
                uint32_t br[4];
                ldm_x4(br, bBase + (uint32_t)(p * 576 * 4) + kOff);
                bf[p * 2 + 0][0] = br[0];
                bf[p * 2 + 0][1] = br[1];
                bf[p * 2 + 1][0] = br[2];
                bf[p * 2 + 1][1] = br[3];
            }
#pragma unroll
            for (int mf = 0; mf < 4; mf++)
#pragma unroll
                for (int nf = 0; nf < 4; nf++) {
                    asm volatile(
                        "mma.sync.aligned.m16n8k16.row.col.f32.f16.f16.f32 "
                        "{%0,%1,%2,%3}, {%4,%5,%6,%7}, {%8,%9}, {%0,%1,%2,%3};"
                        : "+f"(acc[mf][nf][0]), "+f"(acc[mf][nf][1]),
                          "+f"(acc[mf][nf][2]), "+f"(acc[mf][nf][3])
                        : "r"(af[mf][0]), "r"(af[mf][1]), "r"(af[mf][2]), "r"(af[mf][3]),
                          "r"(bf[nf][0]), "r"(bf[nf][1]));
                }
        }
        __syncthreads();
    }

    const int head_loc = wc >> 1;
#pragma unroll
    for (int mf = 0; mf < 4; mf++) {
        const int lrow_lo = wr * 64 + mf * 16 + grp;
        const int lrow_hi = lrow_lo + 8;
        const int grow_lo = m0 + lrow_lo;
        const int grow_hi = m0 + lrow_hi;

        float s_lo = 0.f, v_lo = 0.f, s_hi = 0.f, v_hi = 0.f;
#pragma unroll
        for (int nf = 0; nf < 4; nf++) {
            const int col = colBase + wc * 32 + nf * 8 + t4 * 2;
            const float a0 = atts[col], a1 = atts[col + 1];
            const float d0 = attd[col], d1 = attd[col + 1];
            s_lo = fmaf(acc[mf][nf][0], a0, fmaf(acc[mf][nf][1], a1, s_lo));
            v_lo = fmaf(acc[mf][nf][0], d0, fmaf(acc[mf][nf][1], d1, v_lo));
            s_hi = fmaf(acc[mf][nf][2], a0, fmaf(acc[mf][nf][3], a1, s_hi));
            v_hi = fmaf(acc[mf][nf][2], d0, fmaf(acc[mf][nf][3], d1, v_hi));
            if (grow_lo < M)
                g_xph[(size_t)grow_lo * 128 + (col >> 1)] =
                    __floats2half2_rn(acc[mf][nf][0], acc[mf][nf][1]);
            if (grow_hi < M)
                g_xph[(size_t)grow_hi * 128 + (col >> 1)] =
                    __floats2half2_rn(acc[mf][nf][2], acc[mf][nf][3]);
        }
#pragma unroll
        for (int off = 1; off < 4; off <<= 1) {
            s_lo += __shfl_xor_sync(0xffffffffu, s_lo, off);
            v_lo += __shfl_xor_sync(0xffffffffu, v_lo, off);
            s_hi += __shfl_xor_sync(0xffffffffu, s_hi, off);
            v_hi += __shfl_xor_sync(0xffffffffu, v_hi, off);
        }
        if (t4 == 0) {
            atomicAdd(&part[lrow_lo * 4 + head_loc * 2 + 0], s_lo);
            atomicAdd(&part[lrow_lo * 4 + head_loc * 2 + 1], v_lo);
            atomicAdd(&part[lrow_hi * 4 + head_loc * 2 + 0], s_hi);
            atomicAdd(&part[lrow_hi * 4 + head_loc * 2 + 1], v_hi);
        }
    }
    __syncthreads();

    if (t < 128) {
        const int grow = m0 + t;
        if (grow < M) {
            const int hbase = colBase >> 6;
            g_asrc[grow * 4 + hbase + 0] = part[t * 4 + 0];
            g_adst[grow * 4 + hbase + 0] = part[t * 4 + 1];
            g_asrc[grow * 4 + hbase + 1] = part[t * 4 + 2];
            g_adst[grow * 4 + hbase + 1] = part[t * 4 + 3];
        }
    }
}

// ---------------- aggregate: one warp per destination, single fused pass ------
__global__ __launch_bounds__(256) void aggregate_kernel(const float* __restrict__ bias,
                                                        float* __restrict__ out, int N) {
    const int warp = (blockIdx.x * blockDim.x + threadIdx.x) >> 5;
    const int lane = threadIdx.x & 31;
    if (warp >= N) return;

    const int start = g_rowptr[warp];
    const int end   = g_rowptr[warp + 1];
    const int h = lane >> 3;

    float den = 0.f;
    float acc[8];
#pragma unroll
    for (int j = 0; j < 8; j++) acc[j] = 0.f;

    const uint4* exu = reinterpret_cast<const uint4*>(g_ex);
    int pos = start;

    for (; pos + 4 <= end; pos += 4) {
        int s0 = g_sd[pos + 0].x;
        int s1 = g_sd[pos + 1].x;
        int s2 = g_sd[pos + 2].x;
        int s3 = g_sd[pos + 3].x;
        uint4 e0 = exu[pos + 0];
        uint4 e1 = exu[pos + 1];
        uint4 e2 = exu[pos + 2];
        uint4 e3 = exu[pos + 3];
        uint4 v0 = reinterpret_cast<const uint4*>(g_xph + (size_t)s0 * 128)[lane];
        uint4 v1 = reinterpret_cast<const uint4*>(g_xph + (size_t)s1 * 128)[lane];
        uint4 v2 = reinterpret_cast<const uint4*>(g_xph + (size_t)s2 * 128)[lane];
        uint4 v3 = reinterpret_cast<const uint4*>(g_xph + (size_t)s3 * 128)[lane];
        float c0 = pick_h(e0, h), c1 = pick_h(e1, h), c2 = pick_h(e2, h), c3 = pick_h(e3, h);
        den += (c0 + c1) + (c2 + c3);
#pragma unroll
        for (int q = 0; q < 4; q++) {
            uint32_t w0 = (&v0.x)[q], w1 = (&v1.x)[q], w2 = (&v2.x)[q], w3 = (&v3.x)[q];
            float2 f0 = __half22float2(*reinterpret_cast<__half2*>(&w0));
            float2 f1 = __half22float2(*reinterpret_cast<__half2*>(&w1));
            float2 f2 = __half22float2(*reinterpret_cast<__half2*>(&w2));
            float2 f3 = __half22float2(*reinterpret_cast<__half2*>(&w3));
            acc[q * 2 + 0] = fmaf(f0.x, c0, fmaf(f1.x, c1, fmaf(f2.x, c2, fmaf(f3.x, c3, acc[q * 2 + 0]))));
            acc[q * 2 + 1] = fmaf(f0.y, c0, fmaf(f1.y, c1, fmaf(f2.y, c2, fmaf(f3.y, c3, acc[q * 2 + 1]))));
        }
    }
    for (; pos < end; pos++) {
        int s = g_sd[pos].x;
        uint4 e = exu[pos];
        uint4 v = reinterpret_cast<const uint4*>(g_xph + (size_t)s * 128)[lane];
        float c = pick_h(e, h);
        den += c;
#pragma unroll
        for (int q = 0; q < 4; q++) {
            uint32_t w = (&v.x)[q];
            float2 f = __half22float2(*reinterpret_cast<__half2*>(&w));
            acc[q * 2 + 0] = fmaf(f.x, c, acc[q * 2 + 0]);
            acc[q * 2 + 1] = fmaf(f.y, c, acc[q * 2 + 1]);
        }
    }

    const float inv = 1.f / den;
    const float4 b0 = *reinterpret_cast<const float4*>(&bias[lane * 8]);
    const float4 b1 = *reinterpret_cast<const float4*>(&bias[lane * 8 + 4]);
    float* orow = out + (size_t)warp * 256 + lane * 8;
    *reinterpret_cast<float4*>(orow) =
        make_float4(fmaf(acc[0], inv, b0.x), fmaf(acc[1], inv, b0.y),
                    fmaf(acc[2], inv, b0.z), fmaf(acc[3], inv, b0.w));
    *reinterpret_cast<float4*>(orow + 4) =
        make_float4(fmaf(acc[4], inv, b1.x), fmaf(acc[5], inv, b1.y),
                    fmaf(acc[6], inv, b1.z), fmaf(acc[7], inv, b1.w));
}

// ---------------- launch: fork-join, CSR+fill_idx overlapped with GEMM ---------
extern "C" void kernel_launch(void* const* d_in, const int* in_sizes, int n_in,
                              void* d_out, int out_size) {
    const float* x       = (const float*)d_in[0];
    const float* W       = (const float*)d_in[1];
    const float* att_src = (const float*)d_in[2];
    const float* att_dst = (const float*)d_in[3];
    const float* bias    = (const float*)d_in[4];
    const void*  ei      = d_in[5];
    float*       out     = (float*)d_out;

    const int N  = in_sizes[0] / 128;
    const int E  = in_sizes[5] / 2;
    const int EP = E + N;
    const int nb = (N + SCAN_B - 1) / SCAN_B;

    void* cnt_ptr = nullptr;
    cudaGetSymbolAddress(&cnt_ptr, g_cnt);

    cudaStream_t s1;
    cudaStreamCreateWithFlags(&s1, cudaStreamNonBlocking);
    cudaEvent_t evFork, evJoin;
    cudaEventCreateWithFlags(&evFork, cudaEventDisableTiming);
    cudaEventCreateWithFlags(&evJoin, cudaEventDisableTiming);

    cudaEventRecord(evFork, 0);
    cudaStreamWaitEvent(s1, evFork, 0);

    // CSR branch (independent of GEMM): memset, detect, hist, scan, fill_idx
    cudaMemsetAsync(cnt_ptr, 0, (size_t)N * sizeof(int), s1);
    detect_kernel<<<1, 128, 0, s1>>>((const unsigned int*)ei, E);
    hist_kernel<<<((E + 1) / 2 + 255) / 256, 256, 0, s1>>>(ei, E);
    scan1_kernel<<<nb, SCAN_B, 0, s1>>>(N);
    scan2_kernel<<<1, 128, 0, s1>>>(nb);
    scan3_kernel<<<(N + 255) / 256, 256, 0, s1>>>(N);
    fill_idx_kernel<<<(EP + 255) / 256, 256, 0, s1>>>(ei, E, EP);

    // main branch: GEMM
    cudaFuncSetAttribute(gemm_mma_kernel, cudaFuncAttributeMaxDynamicSharedMemorySize,
                         SMEM_BYTES);
    dim3 ggrid((N + 127) / 128, 2);
    gemm_mma_kernel<<<ggrid, 256, SMEM_BYTES>>>(x, W, att_src, att_dst, N);

    // join: ex needs fill_idx (s1) + GEMM logits (stream 0)
    cudaEventRecord(evJoin, s1);
    cudaStreamWaitEvent(0, evJoin, 0);

    ex_kernel<<<(EP + 255) / 256, 256>>>(EP);
    aggregate_kernel<<<(N * 32 + 255) / 256, 256>>>(bias, out, N);
}